// round 2
// baseline (speedup 1.0000x reference)
#include <cuda_runtime.h>

#define EPS_BN 1e-5f
#define EPS_MI 1e-9f

// Scratch (static device arrays; no allocation allowed)
__device__ float g_trans[2 * 8 * 256 * 256];  // [tensor][b][o][n] conv1 output (post BN+ReLU)
__device__ float g_A[2 * 8 * 256];            // A = sum p*ln p per (tensor,b,c)
__device__ float g_h1e[8 * 256];              // entropy-branch hidden
__device__ float g_h1m[8 * 256];              // mi-branch hidden
__device__ float g_ew[8 * 256];               // sigmoid entropy gate
__device__ float g_mw[8 * 256];               // sigmoid mi gate
__device__ float g_part[8 * 256 * 256];       // conv2 vis partial

__device__ __forceinline__ float sigmoidf(float x) {
    return 1.f / (1.f + __expf(-x));
}

// ---------------------------------------------------------------------------
// K1: conv1 (1x1 conv as GEMM) + BN + ReLU for both vis and text.
// Grid (4,4,16): x = o-tile, y = n-tile, z = tensor*8 + batch. Block 256 thr,
// 64x64 tile, 4x4 per thread, K=256 in steps of 8.
// ---------------------------------------------------------------------------
__global__ __launch_bounds__(256) void conv1_kernel(
    const float* __restrict__ vis, const float* __restrict__ text,
    const float* __restrict__ W, const float* __restrict__ bt,
    const float* __restrict__ g1, const float* __restrict__ b1,
    const float* __restrict__ m1, const float* __restrict__ v1)
{
    __shared__ float As[8][64];
    __shared__ float Bs[8][64];

    const int bm = blockIdx.x * 64;
    const int bn = blockIdx.y * 64;
    const int zb = blockIdx.z;
    const int tensor = zb >> 3, b = zb & 7;
    const float* __restrict__ X = (tensor ? text : vis) + b * 65536;

    const int tid = threadIdx.x;
    const int tx = tid & 15, ty = tid >> 4;

    float acc[4][4] = {};

    for (int c0 = 0; c0 < 256; c0 += 8) {
        #pragma unroll
        for (int t = 0; t < 2; t++) {
            int l = tid + t * 256;
            int i = l >> 3, j = l & 7;
            As[j][i] = W[(bm + i) * 256 + c0 + j];
        }
        #pragma unroll
        for (int t = 0; t < 2; t++) {
            int l = tid + t * 256;
            int j = l >> 6, n = l & 63;
            Bs[j][n] = X[(c0 + j) * 256 + bn + n];
        }
        __syncthreads();
        #pragma unroll
        for (int kk = 0; kk < 8; kk++) {
            float4 a = *(const float4*)&As[kk][ty * 4];
            float4 bv = *(const float4*)&Bs[kk][tx * 4];
            acc[0][0] += a.x * bv.x; acc[0][1] += a.x * bv.y; acc[0][2] += a.x * bv.z; acc[0][3] += a.x * bv.w;
            acc[1][0] += a.y * bv.x; acc[1][1] += a.y * bv.y; acc[1][2] += a.y * bv.z; acc[1][3] += a.y * bv.w;
            acc[2][0] += a.z * bv.x; acc[2][1] += a.z * bv.y; acc[2][2] += a.z * bv.z; acc[2][3] += a.z * bv.w;
            acc[3][0] += a.w * bv.x; acc[3][1] += a.w * bv.y; acc[3][2] += a.w * bv.z; acc[3][3] += a.w * bv.w;
        }
        __syncthreads();
    }

    #pragma unroll
    for (int r = 0; r < 4; r++) {
        int o = bm + ty * 4 + r;
        float s = g1[o] * rsqrtf(v1[o] + EPS_BN);
        float sh = (bt[o] - m1[o]) * s + b1[o];
        float4 y;
        y.x = fmaxf(acc[r][0] * s + sh, 0.f);
        y.y = fmaxf(acc[r][1] * s + sh, 0.f);
        y.z = fmaxf(acc[r][2] * s + sh, 0.f);
        y.w = fmaxf(acc[r][3] * s + sh, 0.f);
        *(float4*)&g_trans[((tensor * 8 + b) * 256 + o) * 256 + bn + tx * 4] = y;
    }
}

// ---------------------------------------------------------------------------
// K2: per-(tensor,b,c) softmax statistics: A = sum p*ln p = S2/S1 - ln S1.
// (entropy H = -A; mi closed form = A_v + A_t). One warp per 256-elem row.
// Grid 512 blocks x 256 threads -> 4096 rows.
// ---------------------------------------------------------------------------
__global__ __launch_bounds__(256) void entropy_kernel()
{
    const int warp = threadIdx.x >> 5, lane = threadIdx.x & 31;
    const int row = blockIdx.x * 8 + warp;
    const float* __restrict__ x = g_trans + row * 256;

    float v[8];
    float mx = -1e30f;
    #pragma unroll
    for (int i = 0; i < 8; i++) { v[i] = x[lane + 32 * i]; mx = fmaxf(mx, v[i]); }
    #pragma unroll
    for (int o = 16; o; o >>= 1) mx = fmaxf(mx, __shfl_xor_sync(0xffffffffu, mx, o));

    float s1 = 0.f, s2 = 0.f;
    #pragma unroll
    for (int i = 0; i < 8; i++) {
        float u = v[i] - mx;
        float e = __expf(u);
        s1 += e;
        s2 += u * e;
    }
    #pragma unroll
    for (int o = 16; o; o >>= 1) {
        s1 += __shfl_xor_sync(0xffffffffu, s1, o);
        s2 += __shfl_xor_sync(0xffffffffu, s2, o);
    }
    if (lane == 0) g_A[row] = s2 / s1 - logf(s1);
}

// ---------------------------------------------------------------------------
// K3a: MLP layer 1 (both branches) + ReLU. Warp computes one output feature j
// for all 8 batches, coalesced reads of W rows, inputs staged in smem.
// Grid 64: bid<32 -> entropy branch (K=512), else mi branch (K=256).
// ---------------------------------------------------------------------------
__global__ __launch_bounds__(256) void mlp1_kernel(
    const float* __restrict__ We1, const float* __restrict__ be1,
    const float* __restrict__ Wm1, const float* __restrict__ bm1)
{
    __shared__ float xs[8 * 512];
    const int bid = blockIdx.x;
    const int branch = bid >> 5;
    const int j = (bid & 31) * 8 + (threadIdx.x >> 5);
    const int lane = threadIdx.x & 31;
    const int K = branch ? 256 : 512;

    if (branch == 0) {
        for (int l = threadIdx.x; l < 8 * 512; l += 256) {
            int b = l >> 9, k = l & 511;
            xs[l] = -g_A[((k < 256) ? 0 : 2048) + b * 256 + (k & 255)];
        }
    } else {
        for (int l = threadIdx.x; l < 8 * 256; l += 256) {
            int b = l >> 8, k = l & 255;
            xs[l] = g_A[b * 256 + k] + g_A[2048 + b * 256 + k];
        }
    }
    __syncthreads();

    const float* __restrict__ Wrow = (branch ? Wm1 : We1) + j * K;
    float acc[8] = {};
    for (int k = lane; k < K; k += 32) {
        float w = Wrow[k];
        #pragma unroll
        for (int b = 0; b < 8; b++) acc[b] += w * xs[b * K + k];
    }
    #pragma unroll
    for (int b = 0; b < 8; b++) {
        #pragma unroll
        for (int o = 16; o; o >>= 1) acc[b] += __shfl_xor_sync(0xffffffffu, acc[b], o);
    }
    if (lane == 0) {
        float bias = branch ? bm1[j] : be1[j];
        float* out = branch ? g_h1m : g_h1e;
        #pragma unroll
        for (int b = 0; b < 8; b++) out[b * 256 + j] = fmaxf(acc[b] + bias, 0.f);
    }
}

// ---------------------------------------------------------------------------
// K3b: MLP layer 2 + sigmoid -> gates ew, mw. Same structure, K=256 both.
// ---------------------------------------------------------------------------
__global__ __launch_bounds__(256) void mlp2_kernel(
    const float* __restrict__ We2, const float* __restrict__ be2,
    const float* __restrict__ Wm2, const float* __restrict__ bm2)
{
    __shared__ float xs[8 * 256];
    const int bid = blockIdx.x;
    const int branch = bid >> 5;
    const int j = (bid & 31) * 8 + (threadIdx.x >> 5);
    const int lane = threadIdx.x & 31;

    const float* __restrict__ hin = branch ? g_h1m : g_h1e;
    for (int l = threadIdx.x; l < 8 * 256; l += 256) xs[l] = hin[l];
    __syncthreads();

    const float* __restrict__ Wrow = (branch ? Wm2 : We2) + j * 256;
    float acc[8] = {};
    for (int k = lane; k < 256; k += 32) {
        float w = Wrow[k];
        #pragma unroll
        for (int b = 0; b < 8; b++) acc[b] += w * xs[b * 256 + k];
    }
    #pragma unroll
    for (int b = 0; b < 8; b++) {
        #pragma unroll
        for (int o = 16; o; o >>= 1) acc[b] += __shfl_xor_sync(0xffffffffu, acc[b], o);
    }
    if (lane == 0) {
        float bias = branch ? bm2[j] : be2[j];
        float* out = branch ? g_mw : g_ew;
        #pragma unroll
        for (int b = 0; b < 8; b++) out[b * 256 + j] = sigmoidf(acc[b] + bias);
    }
}

// ---------------------------------------------------------------------------
// K4: final conv (K=512 split as two K=256 GEMMs over vis/text halves).
// phase 0: partial = Wf[:, :256] @ (vt * ew*mw)          -> g_part
// phase 1: out = relu(BN(partial + Wf[:, 256:] @ (tt*(1-ew)*mw) + bf))
// Grid (4,4,8) per phase.
// ---------------------------------------------------------------------------
__global__ __launch_bounds__(256) void conv2_kernel(
    const float* __restrict__ Wf, const float* __restrict__ bf,
    const float* __restrict__ g2, const float* __restrict__ b2,
    const float* __restrict__ m2, const float* __restrict__ v2,
    float* __restrict__ out, int phase)
{
    __shared__ float As[8][64];
    __shared__ float Bs[8][64];
    __shared__ float sc[256];

    const int bm = blockIdx.x * 64;
    const int bn = blockIdx.y * 64;
    const int b = blockIdx.z;
    const int tid = threadIdx.x;
    const int tx = tid & 15, ty = tid >> 4;

    {
        float e = g_ew[b * 256 + tid], m = g_mw[b * 256 + tid];
        sc[tid] = phase ? (1.f - e) * m : e * m;
    }
    __syncthreads();

    const float* __restrict__ X = g_trans + (phase * 8 + b) * 65536;
    float acc[4][4] = {};

    for (int c0 = 0; c0 < 256; c0 += 8) {
        #pragma unroll
        for (int t = 0; t < 2; t++) {
            int l = tid + t * 256;
            int i = l >> 3, j = l & 7;
            As[j][i] = Wf[(bm + i) * 512 + phase * 256 + c0 + j];
        }
        #pragma unroll
        for (int t = 0; t < 2; t++) {
            int l = tid + t * 256;
            int j = l >> 6, n = l & 63;
            Bs[j][n] = X[(c0 + j) * 256 + bn + n] * sc[c0 + j];
        }
        __syncthreads();
        #pragma unroll
        for (int kk = 0; kk < 8; kk++) {
            float4 a = *(const float4*)&As[kk][ty * 4];
            float4 bv = *(const float4*)&Bs[kk][tx * 4];
            acc[0][0] += a.x * bv.x; acc[0][1] += a.x * bv.y; acc[0][2] += a.x * bv.z; acc[0][3] += a.x * bv.w;
            acc[1][0] += a.y * bv.x; acc[1][1] += a.y * bv.y; acc[1][2] += a.y * bv.z; acc[1][3] += a.y * bv.w;
            acc[2][0] += a.z * bv.x; acc[2][1] += a.z * bv.y; acc[2][2] += a.z * bv.z; acc[2][3] += a.z * bv.w;
            acc[3][0] += a.w * bv.x; acc[3][1] += a.w * bv.y; acc[3][2] += a.w * bv.z; acc[3][3] += a.w * bv.w;
        }
        __syncthreads();
    }

    if (phase == 0) {
        #pragma unroll
        for (int r = 0; r < 4; r++) {
            int o = bm + ty * 4 + r;
            float4 y = make_float4(acc[r][0], acc[r][1], acc[r][2], acc[r][3]);
            *(float4*)&g_part[(b * 256 + o) * 256 + bn + tx * 4] = y;
        }
    } else {
        #pragma unroll
        for (int r = 0; r < 4; r++) {
            int o = bm + ty * 4 + r;
            float s = g2[o] * rsqrtf(v2[o] + EPS_BN);
            float sh = (bf[o] - m2[o]) * s + b2[o];
            float4 p = *(const float4*)&g_part[(b * 256 + o) * 256 + bn + tx * 4];
            float4 y;
            y.x = fmaxf((acc[r][0] + p.x) * s + sh, 0.f);
            y.y = fmaxf((acc[r][1] + p.y) * s + sh, 0.f);
            y.z = fmaxf((acc[r][2] + p.z) * s + sh, 0.f);
            y.w = fmaxf((acc[r][3] + p.w) * s + sh, 0.f);
            *(float4*)&out[(b * 256 + o) * 256 + bn + tx * 4] = y;
        }
    }
}

// ---------------------------------------------------------------------------
extern "C" void kernel_launch(void* const* d_in, const int* in_sizes, int n_in,
                              void* d_out, int out_size)
{
    const float* vis  = (const float*)d_in[0];
    const float* text = (const float*)d_in[1];
    const float* Wt   = (const float*)d_in[2];
    const float* bt   = (const float*)d_in[3];
    const float* g1   = (const float*)d_in[4];
    const float* b1   = (const float*)d_in[5];
    const float* m1   = (const float*)d_in[6];
    const float* v1   = (const float*)d_in[7];
    const float* We1  = (const float*)d_in[8];
    const float* be1  = (const float*)d_in[9];
    const float* We2  = (const float*)d_in[10];
    const float* be2  = (const float*)d_in[11];
    const float* Wm1  = (const float*)d_in[12];
    const float* bm1  = (const float*)d_in[13];
    const float* Wm2  = (const float*)d_in[14];
    const float* bm2  = (const float*)d_in[15];
    const float* Wf   = (const float*)d_in[16];
    const float* bf   = (const float*)d_in[17];
    const float* g2   = (const float*)d_in[18];
    const float* b2   = (const float*)d_in[19];
    const float* m2   = (const float*)d_in[20];
    const float* v2   = (const float*)d_in[21];
    float* out = (float*)d_out;

    conv1_kernel<<<dim3(4, 4, 16), 256>>>(vis, text, Wt, bt, g1, b1, m1, v1);
    entropy_kernel<<<512, 256>>>();
    mlp1_kernel<<<64, 256>>>(We1, be1, Wm1, bm1);
    mlp2_kernel<<<64, 256>>>(We2, be2, Wm2, bm2);
    conv2_kernel<<<dim3(4, 4, 8), 256>>>(Wf, bf, g2, b2, m2, v2, out, 0);
    conv2_kernel<<<dim3(4, 4, 8), 256>>>(Wf, bf, g2, b2, m2, v2, out, 1);
}

// round 6
// speedup vs baseline: 1.1036x; 1.1036x over previous
#include <cuda_runtime.h>

#define EPS_BN 1e-5f

typedef unsigned long long ull;

// Scratch (static device arrays; no allocation allowed)
__device__ float g_trans[2 * 8 * 256 * 256];  // [tensor][b][o][n] conv1 output (post BN+ReLU)
__device__ float g_A[2 * 8 * 256];            // A = sum p*ln p per (tensor,b,c)
__device__ float g_h1e[8 * 256];              // entropy-branch hidden
__device__ float g_h1m[8 * 256];              // mi-branch hidden
__device__ float g_ew[8 * 256];               // sigmoid entropy gate
__device__ float g_mw[8 * 256];               // sigmoid mi gate

__device__ __forceinline__ float sigmoidf(float x) {
    return 1.f / (1.f + __expf(-x));
}

// ---- packed fp32x2 helpers --------------------------------------------------
__device__ __forceinline__ ull pk2(float x) {
    ull r;
    asm("mov.b64 %0, {%1, %1};" : "=l"(r) : "f"(x));
    return r;
}
__device__ __forceinline__ void fma2(ull& d, ull a, ull b) {
    asm("fma.rn.f32x2 %0, %1, %2, %0;" : "+l"(d) : "l"(a), "l"(b));
}
__device__ __forceinline__ float2 upk(ull v) {
    float2 r;
    asm("mov.b64 {%0, %1}, %2;" : "=f"(r.x), "=f"(r.y) : "l"(v));
    return r;
}

// ---------------------------------------------------------------------------
// K1: conv1 (1x1 conv GEMM) + BN + ReLU, both tensors.
// Tile 64(M) x 128(N), 256 threads, per-thread 4x8 via f32x2, K=256 in 8-steps,
// register-staged double buffer. Grid (4,2,16) = 128 blocks.
// ---------------------------------------------------------------------------
__global__ __launch_bounds__(256) void conv1_kernel(
    const float* __restrict__ vis, const float* __restrict__ text,
    const float* __restrict__ W, const float* __restrict__ bt,
    const float* __restrict__ g1, const float* __restrict__ b1,
    const float* __restrict__ m1, const float* __restrict__ v1)
{
    __shared__ __align__(16) float As[2][8][72];   // padded rows (bank spread)
    __shared__ __align__(16) float Bs[2][8][128];

    const int bm = blockIdx.x * 64;
    const int bn = blockIdx.y * 128;
    const int zb = blockIdx.z;
    const int tensor = zb >> 3, b = zb & 7;
    const float* __restrict__ X = (tensor ? text : vis) + b * 65536;

    const int tid = threadIdx.x;
    const int tx = tid & 15, ty = tid >> 4;

    // A staging map: thread -> (iA, jA), loads rows iA and iA+32
    const int iA = tid >> 3, jA = tid & 7;
    const float* __restrict__ pA0 = W + (bm + iA) * 256 + jA;
    // B staging map: thread -> (jB, nB), loads k-rows jB, jB+2, jB+4, jB+6
    const int nB = tid & 127, jB = tid >> 7;
    const float* __restrict__ pB0 = X + jB * 256 + bn + nB;

    float ra0, ra1, rb0, rb1, rb2, rb3;

    // prologue (c0 = 0)
    ra0 = pA0[0];       ra1 = pA0[32 * 256];
    rb0 = pB0[0];       rb1 = pB0[2 * 256];
    rb2 = pB0[4 * 256]; rb3 = pB0[6 * 256];
    As[0][jA][iA] = ra0; As[0][jA][iA + 32] = ra1;
    Bs[0][jB][nB] = rb0; Bs[0][jB + 2][nB] = rb1;
    Bs[0][jB + 4][nB] = rb2; Bs[0][jB + 6][nB] = rb3;
    __syncthreads();

    ull acc[4][4];
    #pragma unroll
    for (int r = 0; r < 4; r++)
        #pragma unroll
        for (int p = 0; p < 4; p++) acc[r][p] = 0ull;

    int buf = 0;
    for (int step = 0; step < 32; step++) {
        const int c0n = (step + 1) * 8;
        if (step < 31) {
            ra0 = pA0[c0n];            ra1 = pA0[32 * 256 + c0n];
            const float* pb = pB0 + c0n * 256;
            rb0 = pb[0];    rb1 = pb[512];
            rb2 = pb[1024]; rb3 = pb[1536];
        }
        #pragma unroll
        for (int kk = 0; kk < 8; kk++) {
            const float4 a4 = *(const float4*)&As[buf][kk][ty * 4];
            const ull ad0 = pk2(a4.x), ad1 = pk2(a4.y), ad2 = pk2(a4.z), ad3 = pk2(a4.w);
            const ulonglong2 bA = *(const ulonglong2*)&Bs[buf][kk][tx * 8];
            const ulonglong2 bB = *(const ulonglong2*)&Bs[buf][kk][tx * 8 + 4];
            fma2(acc[0][0], ad0, bA.x); fma2(acc[0][1], ad0, bA.y);
            fma2(acc[0][2], ad0, bB.x); fma2(acc[0][3], ad0, bB.y);
            fma2(acc[1][0], ad1, bA.x); fma2(acc[1][1], ad1, bA.y);
            fma2(acc[1][2], ad1, bB.x); fma2(acc[1][3], ad1, bB.y);
            fma2(acc[2][0], ad2, bA.x); fma2(acc[2][1], ad2, bA.y);
            fma2(acc[2][2], ad2, bB.x); fma2(acc[2][3], ad2, bB.y);
            fma2(acc[3][0], ad3, bA.x); fma2(acc[3][1], ad3, bA.y);
            fma2(acc[3][2], ad3, bB.x); fma2(acc[3][3], ad3, bB.y);
        }
        if (step < 31) {
            const int nb = buf ^ 1;
            As[nb][jA][iA] = ra0; As[nb][jA][iA + 32] = ra1;
            Bs[nb][jB][nB] = rb0; Bs[nb][jB + 2][nB] = rb1;
            Bs[nb][jB + 4][nB] = rb2; Bs[nb][jB + 6][nB] = rb3;
        }
        __syncthreads();
        buf ^= 1;
    }

    #pragma unroll
    for (int r = 0; r < 4; r++) {
        const int o = bm + ty * 4 + r;
        const float s = g1[o] * rsqrtf(v1[o] + EPS_BN);
        const float sh = (bt[o] - m1[o]) * s + b1[o];
        float y[8];
        #pragma unroll
        for (int p = 0; p < 4; p++) {
            float2 v = upk(acc[r][p]);
            y[2 * p] = fmaxf(v.x * s + sh, 0.f);
            y[2 * p + 1] = fmaxf(v.y * s + sh, 0.f);
        }
        float* dst = &g_trans[(zb * 256 + o) * 256 + bn + tx * 8];
        *(float4*)dst = make_float4(y[0], y[1], y[2], y[3]);
        *(float4*)(dst + 4) = make_float4(y[4], y[5], y[6], y[7]);
    }
}

// ---------------------------------------------------------------------------
// K2: per-(tensor,b,c) softmax stats: A = sum p*ln p = S2/S1 - ln S1.
// One warp per 256-elem row. Grid 512 x 256.
// ---------------------------------------------------------------------------
__global__ __launch_bounds__(256) void entropy_kernel()
{
    const int warp = threadIdx.x >> 5, lane = threadIdx.x & 31;
    const int row = blockIdx.x * 8 + warp;
    const float* __restrict__ x = g_trans + row * 256;

    float v[8];
    float mx = -1e30f;
    #pragma unroll
    for (int i = 0; i < 8; i++) { v[i] = x[lane + 32 * i]; mx = fmaxf(mx, v[i]); }
    #pragma unroll
    for (int o = 16; o; o >>= 1) mx = fmaxf(mx, __shfl_xor_sync(0xffffffffu, mx, o));

    float s1 = 0.f, s2 = 0.f;
    #pragma unroll
    for (int i = 0; i < 8; i++) {
        float u = v[i] - mx;
        float e = __expf(u);
        s1 += e;
        s2 += u * e;
    }
    #pragma unroll
    for (int o = 16; o; o >>= 1) {
        s1 += __shfl_xor_sync(0xffffffffu, s1, o);
        s2 += __shfl_xor_sync(0xffffffffu, s2, o);
    }
    if (lane == 0) g_A[row] = s2 / s1 - logf(s1);
}

// ---------------------------------------------------------------------------
// K3a: MLP layer 1 (+ReLU), both branches, compile-time unrolled K.
// ---------------------------------------------------------------------------
__global__ __launch_bounds__(256) void mlp1_kernel(
    const float* __restrict__ We1, const float* __restrict__ be1,
    const float* __restrict__ Wm1, const float* __restrict__ bm1)
{
    __shared__ float xs[8 * 512];
    const int bid = blockIdx.x;
    const int branch = bid >> 5;
    const int j = (bid & 31) * 8 + (threadIdx.x >> 5);
    const int lane = threadIdx.x & 31;

    float acc[8] = {};

    if (branch == 0) {
        for (int l = threadIdx.x; l < 8 * 512; l += 256) {
            int b = l >> 9, k = l & 511;
            xs[l] = -g_A[((k < 256) ? 0 : 2048) + b * 256 + (k & 255)];
        }
        __syncthreads();
        const float* __restrict__ Wr = We1 + j * 512 + lane;
        #pragma unroll
        for (int i = 0; i < 16; i++) {
            float w = Wr[32 * i];
            #pragma unroll
            for (int b = 0; b < 8; b++) acc[b] += w * xs[b * 512 + lane + 32 * i];
        }
        #pragma unroll
        for (int b = 0; b < 8; b++)
            #pragma unroll
            for (int o = 16; o; o >>= 1) acc[b] += __shfl_xor_sync(0xffffffffu, acc[b], o);
        if (lane == 0) {
            float bias = be1[j];
            #pragma unroll
            for (int b = 0; b < 8; b++) g_h1e[b * 256 + j] = fmaxf(acc[b] + bias, 0.f);
        }
    } else {
        for (int l = threadIdx.x; l < 8 * 256; l += 256) {
            int b = l >> 8, k = l & 255;
            xs[l] = g_A[b * 256 + k] + g_A[2048 + b * 256 + k];
        }
        __syncthreads();
        const float* __restrict__ Wr = Wm1 + j * 256 + lane;
        #pragma unroll
        for (int i = 0; i < 8; i++) {
            float w = Wr[32 * i];
            #pragma unroll
            for (int b = 0; b < 8; b++) acc[b] += w * xs[b * 256 + lane + 32 * i];
        }
        #pragma unroll
        for (int b = 0; b < 8; b++)
            #pragma unroll
            for (int o = 16; o; o >>= 1) acc[b] += __shfl_xor_sync(0xffffffffu, acc[b], o);
        if (lane == 0) {
            float bias = bm1[j];
            #pragma unroll
            for (int b = 0; b < 8; b++) g_h1m[b * 256 + j] = fmaxf(acc[b] + bias, 0.f);
        }
    }
}

// ---------------------------------------------------------------------------
// K3b: MLP layer 2 + sigmoid -> gates ew, mw. K=256 unrolled.
// ---------------------------------------------------------------------------
__global__ __launch_bounds__(256) void mlp2_kernel(
    const float* __restrict__ We2, const float* __restrict__ be2,
    const float* __restrict__ Wm2, const float* __restrict__ bm2)
{
    __shared__ float xs[8 * 256];
    const int bid = blockIdx.x;
    const int branch = bid >> 5;
    const int j = (bid & 31) * 8 + (threadIdx.x >> 5);
    const int lane = threadIdx.x & 31;

    const float* __restrict__ hin = branch ? g_h1m : g_h1e;
    for (int l = threadIdx.x; l < 8 * 256; l += 256) xs[l] = hin[l];
    __syncthreads();

    const float* __restrict__ Wr = (branch ? Wm2 : We2) + j * 256 + lane;
    float acc[8] = {};
    #pragma unroll
    for (int i = 0; i < 8; i++) {
        float w = Wr[32 * i];
        #pragma unroll
        for (int b = 0; b < 8; b++) acc[b] += w * xs[b * 256 + lane + 32 * i];
    }
    #pragma unroll
    for (int b = 0; b < 8; b++)
        #pragma unroll
        for (int o = 16; o; o >>= 1) acc[b] += __shfl_xor_sync(0xffffffffu, acc[b], o);
    if (lane == 0) {
        float bias = branch ? bm2[j] : be2[j];
        float* out = branch ? g_mw : g_ew;
        #pragma unroll
        for (int b = 0; b < 8; b++) out[b * 256 + j] = sigmoidf(acc[b] + bias);
    }
}

// ---------------------------------------------------------------------------
// K4: final conv, single kernel, K=512 (vis half then text half), gates folded
// into the B-operand. Tile 64x64, per-thread 4x4 (f32x2), double-buffered.
// Grid (4,4,8) = 128 blocks.
// ---------------------------------------------------------------------------
__global__ __launch_bounds__(256) void conv2_kernel(
    const float* __restrict__ Wf, const float* __restrict__ bf,
    const float* __restrict__ g2, const float* __restrict__ b2,
    const float* __restrict__ m2, const float* __restrict__ v2,
    float* __restrict__ out)
{
    __shared__ __align__(16) float As[2][8][72];
    __shared__ __align__(16) float Bs[2][8][64];
    __shared__ float sc[512];

    const int bm = blockIdx.x * 64;
    const int bn = blockIdx.y * 64;
    const int b = blockIdx.z;
    const int tid = threadIdx.x;
    const int tx = tid & 15, ty = tid >> 4;

    {
        float e = g_ew[b * 256 + tid], m = g_mw[b * 256 + tid];
        sc[tid] = e * m;
        sc[tid + 256] = (1.f - e) * m;
    }
    __syncthreads();

    const int iA = tid >> 3, jA = tid & 7;
    const float* __restrict__ pA0 = Wf + (bm + iA) * 512 + jA;
    const int nB = tid & 63, jB = tid >> 6;  // jB in 0..3; k-rows jB and jB+4
    const float* __restrict__ Xv = g_trans + b * 65536 + bn + nB;             // vis half
    const float* __restrict__ Xt = g_trans + 8 * 65536 + b * 65536 + bn + nB; // text half

    float ra0, ra1, rb0, rb1;

    // prologue (c0 = 0, vis half)
    ra0 = pA0[0];            ra1 = pA0[32 * 512];
    rb0 = Xv[jB * 256];      rb1 = Xv[(jB + 4) * 256];
    As[0][jA][iA] = ra0; As[0][jA][iA + 32] = ra1;
    Bs[0][jB][nB] = rb0 * sc[jB];
    Bs[0][jB + 4][nB] = rb1 * sc[jB + 4];
    __syncthreads();

    ull acc[4][2];
    #pragma unroll
    for (int r = 0; r < 4; r++) { acc[r][0] = 0ull; acc[r][1] = 0ull; }

    int buf = 0;
    for (int step = 0; step < 64; step++) {
        const int c0n = (step + 1) * 8;
        if (step < 63) {
            ra0 = pA0[c0n];  ra1 = pA0[32 * 512 + c0n];
            const float* pb = (c0n < 256) ? (Xv + c0n * 256) : (Xt + (c0n - 256) * 256);
            rb0 = pb[jB * 256];
            rb1 = pb[(jB + 4) * 256];
        }
        #pragma unroll
        for (int kk = 0; kk < 8; kk++) {
            const float4 a4 = *(const float4*)&As[buf][kk][ty * 4];
            const ull ad0 = pk2(a4.x), ad1 = pk2(a4.y), ad2 = pk2(a4.z), ad3 = pk2(a4.w);
            const ulonglong2 bA = *(const ulonglong2*)&Bs[buf][kk][tx * 4];
            fma2(acc[0][0], ad0, bA.x); fma2(acc[0][1], ad0, bA.y);
            fma2(acc[1][0], ad1, bA.x); fma2(acc[1][1], ad1, bA.y);
            fma2(acc[2][0], ad2, bA.x); fma2(acc[2][1], ad2, bA.y);
            fma2(acc[3][0], ad3, bA.x); fma2(acc[3][1], ad3, bA.y);
        }
        if (step < 63) {
            const int nb = buf ^ 1;
            As[nb][jA][iA] = ra0; As[nb][jA][iA + 32] = ra1;
            Bs[nb][jB][nB] = rb0 * sc[c0n + jB];
            Bs[nb][jB + 4][nB] = rb1 * sc[c0n + jB + 4];
        }
        __syncthreads();
        buf ^= 1;
    }

    #pragma unroll
    for (int r = 0; r < 4; r++) {
        const int o = bm + ty * 4 + r;
        const float s = g2[o] * rsqrtf(v2[o] + EPS_BN);
        const float sh = (bf[o] - m2[o]) * s + b2[o];
        float2 v0 = upk(acc[r][0]);
        float2 v1 = upk(acc[r][1]);
        float4 y;
        y.x = fmaxf(v0.x * s + sh, 0.f);
        y.y = fmaxf(v0.y * s + sh, 0.f);
        y.z = fmaxf(v1.x * s + sh, 0.f);
        y.w = fmaxf(v1.y * s + sh, 0.f);
        *(float4*)&out[(b * 256 + o) * 256 + bn + tx * 4] = y;
    }
}

// ---------------------------------------------------------------------------
extern "C" void kernel_launch(void* const* d_in, const int* in_sizes, int n_in,
                              void* d_out, int out_size)
{
    const float* vis  = (const float*)d_in[0];
    const float* text = (const float*)d_in[1];
    const float* Wt   = (const float*)d_in[2];
    const float* bt   = (const float*)d_in[3];
    const float* g1   = (const float*)d_in[4];
    const float* b1   = (const float*)d_in[5];
    const float* m1   = (const float*)d_in[6];
    const float* v1   = (const float*)d_in[7];
    const float* We1  = (const float*)d_in[8];
    const float* be1  = (const float*)d_in[9];
    const float* We2  = (const float*)d_in[10];
    const float* be2  = (const float*)d_in[11];
    const float* Wm1  = (const float*)d_in[12];
    const float* bm1  = (const float*)d_in[13];
    const float* Wm2  = (const float*)d_in[14];
    const float* bm2  = (const float*)d_in[15];
    const float* Wf   = (const float*)d_in[16];
    const float* bf   = (const float*)d_in[17];
    const float* g2   = (const float*)d_in[18];
    const float* b2   = (const float*)d_in[19];
    const float* m2   = (const float*)d_in[20];
    const float* v2   = (const float*)d_in[21];
    float* out = (float*)d_out;

    conv1_kernel<<<dim3(4, 2, 16), 256>>>(vis, text, Wt, bt, g1, b1, m1, v1);
    entropy_kernel<<<512, 256>>>();
    mlp1_kernel<<<64, 256>>>(We1, be1, Wm1, bm1);
    mlp2_kernel<<<64, 256>>>(We2, be2, Wm2, bm2);
    conv2_kernel<<<dim3(4, 4, 8), 256>>>(Wf, bf, g2, b2, m2, v2, out);
}